// round 9
// baseline (speedup 1.0000x reference)
#include <cuda_runtime.h>
#include <cstdint>

#define KK 64

__device__ __forceinline__ float fast_rcp(float x) {
    float r; asm("rcp.approx.f32 %0, %1;" : "=f"(r) : "f"(x)); return r;
}

__device__ __forceinline__ uint32_t smem_u32(const void* p) {
    uint32_t a;
    asm("{ .reg .u64 t; cvta.to.shared.u64 t, %1; cvt.u32.u64 %0, t; }"
        : "=r"(a) : "l"(p));
    return a;
}

// TWO BATCHES PER 128-THREAD BLOCK (one warp per SMSP, grid=128 <= 148 SMs).
// Half h = threads [64h, 64h+64) owns batch 2*blockIdx.x + h; thread s owns
// state s. Both halves run identical branchless straight-line code, so the
// shared __syncthreads cadence never stalls one half on the other.
//   u_t = (u_{t-1} . M) * exp(emit_t)        (masked steps: u_t = u_{t-1})
//   every 8th step (unconditional): u *= 1/u[0], C += log(u[0])
//   log_Z = C + log(sum_j u_T[j])
__global__ __launch_bounds__(2 * KK, 1) void crf_forward_kernel(
    const int* __restrict__ y, const float* __restrict__ em,
    const float* __restrict__ tr, int Tn, float negInvB,
    float* __restrict__ out)
{
    __shared__ __align__(16) float u_sh[2][2][KK];   // [half][buf][state]
    __shared__ int y_sh[2][1024];                    // [half][T]
    __shared__ float red4[4];                        // per-warp numerators

    const int h = threadIdx.x >> 6;      // half = batch slot in block
    const int s = threadIdx.x & 63;      // state index 0..63
    const int l = threadIdx.x & 31;
    const int b = blockIdx.x * 2 + h;
    const int* yb = y + (size_t)b * Tn;
    const float* eb = em + (size_t)b * Tn * KK;

    // Packed M row for this thread's output state:
    //   Mp[q] = (exp(tr[2q][s]), exp(tr[2q+1][s]))
    unsigned long long Mp[32];
#pragma unroll
    for (int q = 0; q < 32; q++) {
        float m0 = __expf(tr[(2 * q) * KK + s]);
        float m1 = __expf(tr[(2 * q + 1) * KK + s]);
        asm("mov.b64 %0, {%1, %2};" : "=l"(Mp[q]) : "f"(m0), "f"(m1));
    }

    // stage y row in shared (per half)
    for (int t = s; t < Tn; t += KK) y_sh[h][t] = yb[t];

    // u0 = exp(emissions[b,0,:]); own value kept in a register too
    float uown = __expf(eb[s]);
    u_sh[h][0][s] = uown;
    float C = 0.f;
    __syncthreads();

    const uint32_t ubase = smem_u32(&u_sh[h][0][0]);   // already half-offset
    const uint32_t ustore = ubase + (uint32_t)(s << 2);
    const float* ep = eb + s;

    // One recursion step. PSRC/RESC are compile-time in the hot loop.
    // Shared loads/stores are asm volatile: prevents cross-step CSE of the
    // textually-identical unrolled bodies (the R4/R5 bug) and pins ordering.
    auto step = [&](float ecur, int tt, int psrc, bool resc) {
        const int yt = y_sh[h][tt];
        float ex = __expf(ecur);
        float sc = 1.f;
        if (resc) {                       // unconditional rescale (valid always)
            float x0;
            asm volatile("ld.shared.f32 %0, [%1];"
                         : "=f"(x0) : "r"(ubase + (uint32_t)(psrc << 8)));
            sc = fast_rcp(x0);
            C += __logf(x0);
        }
        const float k = ex * sc;          // off the u-dependency chain
        const uint32_t ua = ubase + (uint32_t)(psrc << 8);
        unsigned long long A0 = 0, A1 = 0, A2 = 0, A3 = 0;
#pragma unroll
        for (int g = 0; g < 8; g++) {
            unsigned long long p0, p1, p2, p3;   // u[8g..8g+7] as 4 f32x2 pairs
            asm volatile("ld.shared.v2.u64 {%0, %1}, [%2];"
                : "=l"(p0), "=l"(p1) : "r"(ua + g * 32));
            asm volatile("ld.shared.v2.u64 {%0, %1}, [%2];"
                : "=l"(p2), "=l"(p3) : "r"(ua + g * 32 + 16));
            asm("fma.rn.f32x2 %0, %1, %2, %0;" : "+l"(A0) : "l"(p0), "l"(Mp[4 * g + 0]));
            asm("fma.rn.f32x2 %0, %1, %2, %0;" : "+l"(A1) : "l"(p1), "l"(Mp[4 * g + 1]));
            asm("fma.rn.f32x2 %0, %1, %2, %0;" : "+l"(A2) : "l"(p2), "l"(Mp[4 * g + 2]));
            asm("fma.rn.f32x2 %0, %1, %2, %0;" : "+l"(A3) : "l"(p3), "l"(Mp[4 * g + 3]));
        }
        asm("add.rn.f32x2 %0, %0, %1;" : "+l"(A0) : "l"(A2));
        asm("add.rn.f32x2 %0, %0, %1;" : "+l"(A1) : "l"(A3));
        asm("add.rn.f32x2 %0, %0, %1;" : "+l"(A0) : "l"(A1));
        float lo, hi;
        asm("mov.b64 {%0, %1}, %2;" : "=f"(lo), "=f"(hi) : "l"(A0));
        float dx = (lo + hi) * k;
        // branchless commit (no BSSY/BSYNC in the hot loop)
        uown = (yt != 0) ? dx : uown * sc;
        asm volatile("st.shared.f32 [%0], %1;"
                     :: "r"(ustore + (uint32_t)((psrc ^ 1) << 8)), "f"(uown));
        __syncthreads();
    };

    const int lim = Tn - 1;               // 1023
    auto eld = [&](int t) { return ep[(size_t)t * KK]; };

    // prefetch rows t .. t+7 (no clamps needed: lim >= 8 here)
    float e0 = eld(1), e1 = eld(2), e2 = eld(3), e3 = eld(4);
    float e4 = eld(5), e5 = eld(6), e6 = eld(7), e7 = eld(8);

    int t = 1;
    // main loop: t ≡ 1 (mod 8); parity at entry always 0; rescale at t+7 (≡0 mod 8)
    for (; t + 15 <= lim; t += 8) {
        float n0 = eld(t + 8),  n1 = eld(t + 9),  n2 = eld(t + 10), n3 = eld(t + 11);
        float n4 = eld(t + 12), n5 = eld(t + 13), n6 = eld(t + 14), n7 = eld(t + 15);
        step(e0, t,     0, false);
        step(e1, t + 1, 1, false);
        step(e2, t + 2, 0, false);
        step(e3, t + 3, 1, false);
        step(e4, t + 4, 0, false);
        step(e5, t + 5, 1, false);
        step(e6, t + 6, 0, false);
        step(e7, t + 7, 1, true);
        e0 = n0; e1 = n1; e2 = n2; e3 = n3;
        e4 = n4; e5 = n5; e6 = n6; e7 = n7;
    }

    // tail: runtime parity / rescale; shift-register prefetch with clamped loads
    int p = 0;                             // (t-1) is a multiple of 8 here
    for (; t <= lim; t++) {
        float nn = eld(min(t + 8, lim));
        step(e0, t, p, (t & 7) == 0);
        p ^= 1;
        e0 = e1; e1 = e2; e2 = e3; e3 = e4;
        e4 = e5; e5 = e6; e6 = e7; e7 = nn;
    }
    // final buffer parity: lim steps total from parity 0
    const int pf = lim & 1;

    // (last step ended with __syncthreads; u_sh[h][pf] is visible)

    // log_Z = C + log(sum u)   (redundant per-thread; identical result)
    float ssum = 0.f;
    const float4* uf = reinterpret_cast<const float4*>(&u_sh[h][pf][0]);
#pragma unroll
    for (int q = 0; q < KK / 4; q++) {
        float4 uu = uf[q];
        ssum += (uu.x + uu.y) + (uu.z + uu.w);
    }
    float logz = C + __logf(ssum);

    // numerator: emission + transition scores along the gold path (masked)
    float num = 0.f;
    for (int tt = s; tt < Tn; tt += KK) {
        int yt = y_sh[h][tt];
        if (yt != 0) {
            num += eb[(size_t)tt * KK + yt];
            if (tt > 0) num += tr[y_sh[h][tt - 1] * KK + yt];
        }
    }
#pragma unroll
    for (int o = 16; o > 0; o >>= 1) num += __shfl_xor_sync(0xffffffffu, num, o);
    if (l == 0) red4[threadIdx.x >> 5] = num;
    __syncthreads();
    if (s == 0) {
        float ll = (red4[2 * h] + red4[2 * h + 1]) - logz;
        atomicAdd(out, ll * negInvB);      // out pre-zeroed via memsetAsync
    }
}

extern "C" void kernel_launch(void* const* d_in, const int* in_sizes, int n_in,
                              void* d_out, int out_size)
{
    const int*   y  = (const int*)d_in[0];
    const float* em = (const float*)d_in[1];
    const float* tr = (const float*)d_in[2];

    const int Tn = 1024;                 // problem shape: B=256, T=1024, K=64
    const int B  = in_sizes[0] / Tn;

    cudaMemsetAsync(d_out, 0, sizeof(float));
    crf_forward_kernel<<<B / 2, 2 * KK>>>(y, em, tr, Tn, -1.0f / (float)B,
                                          (float*)d_out);
}

// round 10
// speedup vs baseline: 1.1139x; 1.1139x over previous
#include <cuda_runtime.h>
#include <cstdint>

#define KK 64

__device__ __forceinline__ float fast_rcp(float x) {
    float r; asm("rcp.approx.f32 %0, %1;" : "=f"(r) : "f"(x)); return r;
}

__device__ __forceinline__ uint32_t smem_u32(const void* p) {
    uint32_t a;
    asm("{ .reg .u64 t; cvta.to.shared.u64 t, %1; cvt.u32.u64 %0, t; }"
        : "=r"(a) : "l"(p));
    return a;
}

// TWO INDEPENDENT BATCHES PER 128-THREAD BLOCK (grid=128 <= 148 SMs, so one
// block per SM and one warp per SMSP — no SMSP stacking). Half h = threads
// [64h, 64h+64) owns batch 2*bid+h; thread s owns state s. The two halves are
// FULLY DECOUPLED: each half syncs its own 2 warps with a named barrier
// (bar.sync h+1, 64); there is no block-wide barrier anywhere, so jitter in
// one chain never stalls the other (the R9 regression mechanism).
//   u_t = (u_{t-1} . M) * exp(emit_t)        (masked steps: u_t = u_{t-1})
//   every 8th step (unconditional): u *= 1/u[0], C += log(u[0])
//   log_Z = C + log(sum_j u_T[j])
__global__ __launch_bounds__(2 * KK, 1) void crf_forward_kernel(
    const int* __restrict__ y, const float* __restrict__ em,
    const float* __restrict__ tr, int Tn, float negInvB,
    float* __restrict__ out)
{
    __shared__ __align__(16) float u_sh[2][2][KK];   // [half][buf][state]
    __shared__ int y_sh[2][1024];                    // [half][T]
    __shared__ float red4[4];                        // per-warp numerators

    const int h = threadIdx.x >> 6;      // half = batch slot in block
    const int s = threadIdx.x & 63;      // state index 0..63
    const int l = threadIdx.x & 31;
    const int b = blockIdx.x * 2 + h;
    const int barid = h + 1;             // named barrier id for this half
    const int* yb = y + (size_t)b * Tn;
    const float* eb = em + (size_t)b * Tn * KK;

    auto half_bar = [&]() {
        asm volatile("bar.sync %0, 64;" :: "r"(barid) : "memory");
    };

    // Packed M row for this thread's output state:
    //   Mp[q] = (exp(tr[2q][s]), exp(tr[2q+1][s]))
    unsigned long long Mp[32];
#pragma unroll
    for (int q = 0; q < 32; q++) {
        float m0 = __expf(tr[(2 * q) * KK + s]);
        float m1 = __expf(tr[(2 * q + 1) * KK + s]);
        asm("mov.b64 %0, {%1, %2};" : "=l"(Mp[q]) : "f"(m0), "f"(m1));
    }

    // stage y row in shared (per half)
    for (int t = s; t < Tn; t += KK) y_sh[h][t] = yb[t];

    // u0 = exp(emissions[b,0,:]); own value kept in a register too
    float uown = __expf(eb[s]);
    u_sh[h][0][s] = uown;
    float C = 0.f;
    half_bar();

    const uint32_t ubase = smem_u32(&u_sh[h][0][0]);   // already half-offset
    const uint32_t ustore = ubase + (uint32_t)(s << 2);
    const float* ep = eb + s;

    // One recursion step. PSRC/RESC are compile-time in the hot loop.
    // Shared loads/stores are asm volatile: prevents cross-step CSE of the
    // textually-identical unrolled bodies (the R4/R5 bug) and pins ordering.
    auto step = [&](float ecur, int tt, int psrc, bool resc) {
        const int yt = y_sh[h][tt];
        float ex = __expf(ecur);
        float sc = 1.f;
        if (resc) {                       // unconditional rescale (valid always)
            float x0;
            asm volatile("ld.shared.f32 %0, [%1];"
                         : "=f"(x0) : "r"(ubase + (uint32_t)(psrc << 8)));
            sc = fast_rcp(x0);
            C += __logf(x0);
        }
        const float k = ex * sc;          // off the u-dependency chain
        const uint32_t ua = ubase + (uint32_t)(psrc << 8);
        unsigned long long A0 = 0, A1 = 0, A2 = 0, A3 = 0;
#pragma unroll
        for (int g = 0; g < 8; g++) {
            unsigned long long p0, p1, p2, p3;   // u[8g..8g+7] as 4 f32x2 pairs
            asm volatile("ld.shared.v2.u64 {%0, %1}, [%2];"
                : "=l"(p0), "=l"(p1) : "r"(ua + g * 32));
            asm volatile("ld.shared.v2.u64 {%0, %1}, [%2];"
                : "=l"(p2), "=l"(p3) : "r"(ua + g * 32 + 16));
            asm("fma.rn.f32x2 %0, %1, %2, %0;" : "+l"(A0) : "l"(p0), "l"(Mp[4 * g + 0]));
            asm("fma.rn.f32x2 %0, %1, %2, %0;" : "+l"(A1) : "l"(p1), "l"(Mp[4 * g + 1]));
            asm("fma.rn.f32x2 %0, %1, %2, %0;" : "+l"(A2) : "l"(p2), "l"(Mp[4 * g + 2]));
            asm("fma.rn.f32x2 %0, %1, %2, %0;" : "+l"(A3) : "l"(p3), "l"(Mp[4 * g + 3]));
        }
        asm("add.rn.f32x2 %0, %0, %1;" : "+l"(A0) : "l"(A2));
        asm("add.rn.f32x2 %0, %0, %1;" : "+l"(A1) : "l"(A3));
        asm("add.rn.f32x2 %0, %0, %1;" : "+l"(A0) : "l"(A1));
        float lo, hi;
        asm("mov.b64 {%0, %1}, %2;" : "=f"(lo), "=f"(hi) : "l"(A0));
        float dx = (lo + hi) * k;
        // branchless commit (no BSSY/BSYNC in the hot loop)
        uown = (yt != 0) ? dx : uown * sc;
        asm volatile("st.shared.f32 [%0], %1;"
                     :: "r"(ustore + (uint32_t)((psrc ^ 1) << 8)), "f"(uown));
        half_bar();
    };

    const int lim = Tn - 1;               // 1023
    auto eld = [&](int t) { return ep[(size_t)t * KK]; };

    // prefetch rows t .. t+7 (no clamps needed: lim >= 8 here)
    float e0 = eld(1), e1 = eld(2), e2 = eld(3), e3 = eld(4);
    float e4 = eld(5), e5 = eld(6), e6 = eld(7), e7 = eld(8);

    int t = 1;
    // main loop: t ≡ 1 (mod 8); parity at entry always 0; rescale at t+7 (≡0 mod 8)
    for (; t + 15 <= lim; t += 8) {
        float n0 = eld(t + 8),  n1 = eld(t + 9),  n2 = eld(t + 10), n3 = eld(t + 11);
        float n4 = eld(t + 12), n5 = eld(t + 13), n6 = eld(t + 14), n7 = eld(t + 15);
        step(e0, t,     0, false);
        step(e1, t + 1, 1, false);
        step(e2, t + 2, 0, false);
        step(e3, t + 3, 1, false);
        step(e4, t + 4, 0, false);
        step(e5, t + 5, 1, false);
        step(e6, t + 6, 0, false);
        step(e7, t + 7, 1, true);
        e0 = n0; e1 = n1; e2 = n2; e3 = n3;
        e4 = n4; e5 = n5; e6 = n6; e7 = n7;
    }

    // tail: runtime parity / rescale; shift-register prefetch with clamped loads
    int p = 0;                             // (t-1) is a multiple of 8 here
    for (; t <= lim; t++) {
        float nn = eld(min(t + 8, lim));
        step(e0, t, p, (t & 7) == 0);
        p ^= 1;
        e0 = e1; e1 = e2; e2 = e3; e3 = e4;
        e4 = e5; e5 = e6; e6 = e7; e7 = nn;
    }
    // final buffer parity: lim steps total from parity 0
    const int pf = lim & 1;

    // (last step ended with half_bar; u_sh[h][pf] is visible to this half)

    // log_Z = C + log(sum u)   (redundant per-thread; identical result)
    float ssum = 0.f;
    const float4* uf = reinterpret_cast<const float4*>(&u_sh[h][pf][0]);
#pragma unroll
    for (int q = 0; q < KK / 4; q++) {
        float4 uu = uf[q];
        ssum += (uu.x + uu.y) + (uu.z + uu.w);
    }
    float logz = C + __logf(ssum);

    // numerator: emission + transition scores along the gold path (masked)
    float num = 0.f;
    for (int tt = s; tt < Tn; tt += KK) {
        int yt = y_sh[h][tt];
        if (yt != 0) {
            num += eb[(size_t)tt * KK + yt];
            if (tt > 0) num += tr[y_sh[h][tt - 1] * KK + yt];
        }
    }
#pragma unroll
    for (int o = 16; o > 0; o >>= 1) num += __shfl_xor_sync(0xffffffffu, num, o);
    if (l == 0) red4[threadIdx.x >> 5] = num;
    half_bar();
    if (s == 0) {
        float ll = (red4[2 * h] + red4[2 * h + 1]) - logz;
        atomicAdd(out, ll * negInvB);      // out pre-zeroed via memsetAsync
    }
}

extern "C" void kernel_launch(void* const* d_in, const int* in_sizes, int n_in,
                              void* d_out, int out_size)
{
    const int*   y  = (const int*)d_in[0];
    const float* em = (const float*)d_in[1];
    const float* tr = (const float*)d_in[2];

    const int Tn = 1024;                 // problem shape: B=256, T=1024, K=64
    const int B  = in_sizes[0] / Tn;

    cudaMemsetAsync(d_out, 0, sizeof(float));
    crf_forward_kernel<<<B / 2, 2 * KK>>>(y, em, tr, Tn, -1.0f / (float)B,
                                          (float*)d_out);
}